// round 1
// baseline (speedup 1.0000x reference)
#include <cuda_runtime.h>
#include <cuda_bf16.h>

// ---------------- scratch (static device globals; no allocation) ----------------
__device__ float g_FAT[128 * 4096];     // [k][j] : FA^T = (F @ hW1[1:] + hb1)^T, 2 MB
__device__ float g_stats[4096 * 4];     // per j: ma, m2a, mwa, pad
__device__ float g_part[32 * 128 * 64]; // [jt][b][d] partial masked pools, 1 MB

#define EPS 1e-5f

// ============================================================================
// K0: FA[j][k] = hb1[k] + sum_d F[j][d] * hW1[1+d][k], stored transposed.
// Also per-j stats: ma = mean_k(FA), m2a = mean(FA^2), mwa = mean(w0*FA).
// Grid: 128 blocks x 128 threads; each block handles 32 consecutive j.
// ============================================================================
__global__ __launch_bounds__(128) void k0_precompute(
    const float* __restrict__ F, const float* __restrict__ hW1,
    const float* __restrict__ hb1)
{
    __shared__ float w1s[64 * 128];   // hW1 rows 1..64
    __shared__ float w0s[128];
    __shared__ float hb1s[128];
    __shared__ float fs[64];
    __shared__ float red[12];

    const int tid = threadIdx.x;
    for (int i = tid; i < 64 * 128; i += 128) w1s[i] = hW1[128 + i];
    w0s[tid]  = hW1[tid];
    hb1s[tid] = hb1[tid];
    __syncthreads();

    const int j0 = blockIdx.x * 32;
    for (int jj = 0; jj < 32; jj++) {
        const int j = j0 + jj;
        if (tid < 64) fs[tid] = F[j * 64 + tid];
        __syncthreads();

        float a = hb1s[tid];
        #pragma unroll
        for (int d = 0; d < 64; d++) a += fs[d] * w1s[d * 128 + tid];
        g_FAT[tid * 4096 + j] = a;

        // block reduce: sum a, a^2, w0*a over k=0..127
        float s = a, s2 = a * a, sw = w0s[tid] * a;
        #pragma unroll
        for (int o = 16; o > 0; o >>= 1) {
            s  += __shfl_xor_sync(0xffffffffu, s,  o);
            s2 += __shfl_xor_sync(0xffffffffu, s2, o);
            sw += __shfl_xor_sync(0xffffffffu, sw, o);
        }
        const int w = tid >> 5;
        if ((tid & 31) == 0) { red[w] = s; red[4 + w] = s2; red[8 + w] = sw; }
        __syncthreads();
        if (tid == 0) {
            float S  = red[0] + red[1] + red[2]  + red[3];
            float S2 = red[4] + red[5] + red[6]  + red[7];
            float SW = red[8] + red[9] + red[10] + red[11];
            g_stats[4 * j + 0] = S  * (1.f / 128.f);
            g_stats[4 * j + 1] = S2 * (1.f / 128.f);
            g_stats[4 * j + 2] = SW * (1.f / 128.f);
            g_stats[4 * j + 3] = 0.f;
        }
        __syncthreads();
    }
}

// ============================================================================
// K1: fused main kernel. Block = (b, jt): 128 j's for one b.
//   phase1: hT[k][j] = relu(LN1(x*w0 + FA)) via analytic LN stats
//   phase2: g[j][d] = hT^T @ W2 (128x64x128 register-blocked SGEMM) + hb2
//   phase3: LN2 + affine + relu, masked accumulate over j -> g_part[jt][b][:]
// Dynamic smem layout (floats):
//   [0, 8192)            W2s  [k][d] 128x64
//   [8192, 8192+16896)   hTs  [k][j] stride 132   (reused as gs [j][d] stride 67)
//   tail: small arrays
// ============================================================================
#define K1_W2_OFF   0
#define K1_HT_OFF   8192
#define K1_HT_STRIDE 132
#define K1_TAIL     (8192 + 128 * K1_HT_STRIDE)   // 25088
#define K1_SMEM_FLOATS (K1_TAIL + 1360)
#define K1_SMEM_BYTES  (K1_SMEM_FLOATS * 4)

__global__ __launch_bounds__(256) void k1_main(
    const float* __restrict__ x, const int* __restrict__ mask,
    const float* __restrict__ hW1, const float* __restrict__ hg1,
    const float* __restrict__ hbt1, const float* __restrict__ hW2,
    const float* __restrict__ hb2, const float* __restrict__ hg2,
    const float* __restrict__ hbt2)
{
    extern __shared__ float sm[];
    float* W2s  = sm + K1_W2_OFF;
    float* hTs  = sm + K1_HT_OFF;
    float* w0s  = sm + K1_TAIL;            // 128
    float* g1s  = w0s + 128;               // 128
    float* bt1s = g1s + 128;               // 128
    float* b2s  = bt1s + 128;              // 64
    float* g2s  = b2s + 64;                // 64
    float* bt2s = g2s + 64;                // 64
    float* mu_s = bt2s + 64;               // 128
    float* s_s  = mu_s + 128;              // 128
    float* x_s  = s_s + 128;               // 128
    float* wm_s = x_s + 128;               // 128
    float* mu2  = wm_s + 128;              // 128
    float* is2  = mu2 + 128;               // 128
    float* mwvw = is2 + 128;               // 2

    const int tid = threadIdx.x;
    const int b = blockIdx.x;
    const int jt = blockIdx.y;
    const int jbase = jt * 128;

    if (tid < 128) {
        w0s[tid] = hW1[tid]; g1s[tid] = hg1[tid]; bt1s[tid] = hbt1[tid];
    } else {
        int t = tid - 128;
        if (t < 64) { b2s[t] = hb2[t]; g2s[t] = hg2[t]; bt2s[t] = hbt2[t]; }
    }
    for (int i = tid; i < 8192; i += 256) W2s[i] = hW2[i];
    __syncthreads();

    // mean/var of w0 (once per block; tiny)
    if (tid < 32) {
        float s = 0.f, s2 = 0.f;
        for (int k = tid; k < 128; k += 32) { float w = w0s[k]; s += w; s2 += w * w; }
        #pragma unroll
        for (int o = 16; o > 0; o >>= 1) {
            s  += __shfl_xor_sync(0xffffffffu, s,  o);
            s2 += __shfl_xor_sync(0xffffffffu, s2, o);
        }
        if (tid == 0) {
            float mw = s * (1.f / 128.f);
            mwvw[0] = mw; mwvw[1] = s2 * (1.f / 128.f) - mw * mw;
        }
    }
    __syncthreads();

    // analytic LN1 stats per j
    if (tid < 128) {
        const int j = jbase + tid;
        const float xv = x[b * 4096 + j];
        const float4 st = *reinterpret_cast<const float4*>(&g_stats[4 * j]);
        const float mw = mwvw[0], vw = mwvw[1];
        const float mu = xv * mw + st.x;
        const float var = xv * xv * vw + 2.f * xv * (st.z - mw * st.x)
                        + (st.y - st.x * st.x);
        mu_s[tid] = mu;
        s_s[tid]  = rsqrtf(var + EPS);
        x_s[tid]  = xv;
        wm_s[tid] = (mask[b * 4096 + j] > 0) ? 1.f : 0.f;
    }
    __syncthreads();

    // phase1: build relu(LN1) tile, transposed [k][j]
    #pragma unroll 4
    for (int i = 0; i < 64; i++) {
        const int idx = i * 256 + tid;
        const int k = idx >> 7;
        const int j = idx & 127;
        const float fa = g_FAT[k * 4096 + jbase + j];
        const float v = (w0s[k] * x_s[j] + fa - mu_s[j]) * s_s[j] * g1s[k] + bt1s[k];
        hTs[k * K1_HT_STRIDE + j] = fmaxf(v, 0.f);
    }
    __syncthreads();

    // phase2: 128x64x128 SGEMM, 8x4 register tile per thread
    const int tx = tid & 15;        // 16 -> 64 cols
    const int ty = tid >> 4;        // 16 -> 128 rows
    float acc[8][4];
    #pragma unroll
    for (int r = 0; r < 8; r++)
        #pragma unroll
        for (int c = 0; c < 4; c++) acc[r][c] = 0.f;

    #pragma unroll 4
    for (int k = 0; k < 128; k++) {
        const float4 a0 = *reinterpret_cast<const float4*>(hTs + k * K1_HT_STRIDE + ty * 8);
        const float4 a1 = *reinterpret_cast<const float4*>(hTs + k * K1_HT_STRIDE + ty * 8 + 4);
        const float4 bv = *reinterpret_cast<const float4*>(W2s + k * 64 + tx * 4);
        const float av[8] = {a0.x, a0.y, a0.z, a0.w, a1.x, a1.y, a1.z, a1.w};
        const float bb[4] = {bv.x, bv.y, bv.z, bv.w};
        #pragma unroll
        for (int r = 0; r < 8; r++)
            #pragma unroll
            for (int c = 0; c < 4; c++) acc[r][c] += av[r] * bb[c];
    }
    __syncthreads();   // all reads of hTs done; reuse as gs

    // write g = acc + hb2 into gs [j][d] stride 67
    float* gs = hTs;
    #pragma unroll
    for (int r = 0; r < 8; r++) {
        const int j = ty * 8 + r;
        #pragma unroll
        for (int c = 0; c < 4; c++)
            gs[j * 67 + tx * 4 + c] = acc[r][c] + b2s[tx * 4 + c];
    }
    __syncthreads();

    // LN2 stats per row
    if (tid < 128) {
        float s = 0.f, s2 = 0.f;
        #pragma unroll 4
        for (int d = 0; d < 64; d++) { float g = gs[tid * 67 + d]; s += g; s2 += g * g; }
        const float mu = s * (1.f / 64.f);
        const float var = s2 * (1.f / 64.f) - mu * mu;
        mu2[tid] = mu;
        is2[tid] = rsqrtf(var + EPS);
    }
    __syncthreads();

    // masked pool over the 128 j's
    if (tid < 64) {
        float a = 0.f;
        #pragma unroll 4
        for (int j = 0; j < 128; j++) {
            const float v = (gs[j * 67 + tid] - mu2[j]) * is2[j] * g2s[tid] + bt2s[tid];
            a += wm_s[j] * fmaxf(v, 0.f);
        }
        g_part[(jt * 128 + b) * 64 + tid] = a;
    }
}

// ============================================================================
// K2: per-b reduction + head MLP. 128 blocks x 256 threads.
// ============================================================================
__global__ __launch_bounds__(256) void k2_head(
    const int* __restrict__ mask,
    const float* __restrict__ eW1, const float* __restrict__ eb1,
    const float* __restrict__ eW2, const float* __restrict__ eb2,
    float* __restrict__ out)
{
    __shared__ float c_s[64];
    __shared__ float e_s[256];
    __shared__ float red[16];
    __shared__ int   redi[8];
    __shared__ float os[64];
    __shared__ float sc[4];

    const int b = blockIdx.x;
    const int tid = threadIdx.x;

    // observed count
    int cnt = 0;
    for (int i = tid; i < 4096; i += 256) cnt += (mask[b * 4096 + i] > 0);
    #pragma unroll
    for (int o = 16; o > 0; o >>= 1) cnt += __shfl_xor_sync(0xffffffffu, cnt, o);
    if ((tid & 31) == 0) redi[tid >> 5] = cnt;

    // pooled partial reduction (deterministic fixed order)
    float s = 0.f;
    if (tid < 64) {
        #pragma unroll
        for (int jt = 0; jt < 32; jt++) s += g_part[(jt * 128 + b) * 64 + tid];
    }
    __syncthreads();
    if (tid == 0) {
        int c = 0;
        #pragma unroll
        for (int w = 0; w < 8; w++) c += redi[w];
        sc[0] = fmaxf((float)c, 1.f);
    }
    __syncthreads();
    if (tid < 64) c_s[tid] = s / sc[0];
    __syncthreads();

    // e = relu(LN_na(c @ eW1 + eb1)), E = 256
    float t = eb1[tid];
    #pragma unroll 4
    for (int d = 0; d < 64; d++) t += c_s[d] * eW1[d * 256 + tid];
    {
        float s1 = t, s2 = t * t;
        #pragma unroll
        for (int o = 16; o > 0; o >>= 1) {
            s1 += __shfl_xor_sync(0xffffffffu, s1, o);
            s2 += __shfl_xor_sync(0xffffffffu, s2, o);
        }
        if ((tid & 31) == 0) { red[tid >> 5] = s1; red[8 + (tid >> 5)] = s2; }
        __syncthreads();
        if (tid == 0) {
            float S1 = 0.f, S2 = 0.f;
            #pragma unroll
            for (int w = 0; w < 8; w++) { S1 += red[w]; S2 += red[8 + w]; }
            const float mu = S1 * (1.f / 256.f);
            const float var = S2 * (1.f / 256.f) - mu * mu;
            sc[1] = mu; sc[2] = rsqrtf(var + EPS);
        }
        __syncthreads();
    }
    e_s[tid] = fmaxf(0.f, (t - sc[1]) * sc[2]);
    __syncthreads();

    // out = relu(LN_na(e @ eW2 + eb2)), 64 outputs
    if (tid < 64) {
        float o = eb2[tid];
        #pragma unroll 4
        for (int i = 0; i < 256; i++) o += e_s[i] * eW2[i * 64 + tid];
        os[tid] = o;
    }
    __syncthreads();
    if (tid < 32) {
        const float a = os[tid], c = os[tid + 32];
        float s1 = a + c, s2 = a * a + c * c;
        #pragma unroll
        for (int o = 16; o > 0; o >>= 1) {
            s1 += __shfl_xor_sync(0xffffffffu, s1, o);
            s2 += __shfl_xor_sync(0xffffffffu, s2, o);
        }
        if (tid == 0) {
            const float mu = s1 * (1.f / 64.f);
            const float var = s2 * (1.f / 64.f) - mu * mu;
            sc[1] = mu; sc[2] = rsqrtf(var + EPS);
        }
    }
    __syncthreads();
    if (tid < 64) {
        const float v = fmaxf(0.f, (os[tid] - sc[1]) * sc[2]);
        if (tid < 32) out[b * 32 + tid] = v;                   // mu
        else          out[128 * 32 + b * 32 + (tid - 32)] = v; // logvar
    }
}

// ============================================================================
extern "C" void kernel_launch(void* const* d_in, const int* in_sizes, int n_in,
                              void* d_out, int out_size)
{
    const float* x    = (const float*)d_in[0];
    const int*   mask = (const int*)  d_in[1];
    const float* F    = (const float*)d_in[2];
    const float* hW1  = (const float*)d_in[3];
    const float* hb1  = (const float*)d_in[4];
    const float* hg1  = (const float*)d_in[5];
    const float* hbt1 = (const float*)d_in[6];
    const float* hW2  = (const float*)d_in[7];
    const float* hb2  = (const float*)d_in[8];
    const float* hg2  = (const float*)d_in[9];
    const float* hbt2 = (const float*)d_in[10];
    const float* eW1  = (const float*)d_in[11];
    const float* eb1  = (const float*)d_in[12];
    const float* eW2  = (const float*)d_in[13];
    const float* eb2  = (const float*)d_in[14];
    float* out = (float*)d_out;

    cudaFuncSetAttribute(k1_main, cudaFuncAttributeMaxDynamicSharedMemorySize,
                         K1_SMEM_BYTES);

    k0_precompute<<<128, 128>>>(F, hW1, hb1);
    dim3 g1(128, 32);
    k1_main<<<g1, 256, K1_SMEM_BYTES>>>(x, mask, hW1, hg1, hbt1, hW2,
                                        hb2, hg2, hbt2);
    k2_head<<<128, 256>>>(mask, eW1, eb1, eW2, eb2, out);
}

// round 4
// speedup vs baseline: 1.2481x; 1.2481x over previous
#include <cuda_runtime.h>
#include <cuda_bf16.h>

// ---------------- scratch (static device globals; no allocation) ----------------
__device__ float g_FAT[128 * 4096];     // [k][j] : FA^T = (F @ hW1[1:] + hb1)^T, 2 MB
__device__ float g_stats[4096 * 4];     // per j: ma, m2a, mwa, pad
__device__ float g_part[32 * 128 * 64]; // [jt][b][d] partial masked pools, 1 MB

#define EPS 1e-5f

__device__ __forceinline__ unsigned long long ffma2(
    unsigned long long a, unsigned long long b, unsigned long long c)
{
    unsigned long long d;
    asm("fma.rn.f32x2 %0, %1, %2, %3;" : "=l"(d) : "l"(a), "l"(b), "l"(c));
    return d;
}
__device__ __forceinline__ unsigned long long pack2(float x)
{
    unsigned long long d;
    asm("mov.b64 %0, {%1, %1};" : "=l"(d) : "f"(x));
    return d;
}
__device__ __forceinline__ void unpack2(unsigned long long v, float& lo, float& hi)
{
    asm("mov.b64 {%0, %1}, %2;" : "=f"(lo), "=f"(hi) : "l"(v));
}

// ============================================================================
// K0: FA[j][k] = hb1[k] + sum_d F[j][d] * hW1[1+d][k], stored transposed, plus
// per-j stats (ma, m2a, mwa). Grid 128 blocks x 256 thr; block = 32 j, all k.
// Thread (j = tid&31, kg = tid>>5) computes 16 k's; stats reduced via smem.
// ============================================================================
__global__ __launch_bounds__(256) void k0_precompute(
    const float* __restrict__ F, const float* __restrict__ hW1,
    const float* __restrict__ hb1)
{
    __shared__ float w1s[64 * 128];     // hW1 rows 1..64
    __shared__ float fs[32 * 65];       // F tile, padded stride 65
    __shared__ float w0s[128];
    __shared__ float hb1s[128];
    __shared__ float redS[8][32], redS2[8][32], redSW[8][32];

    const int tid = threadIdx.x;
    const int jbase = blockIdx.x * 32;

    for (int i = tid; i < 64 * 128; i += 256) w1s[i] = hW1[128 + i];
    if (tid < 128) { w0s[tid] = hW1[tid]; hb1s[tid] = hb1[tid]; }
    for (int i = tid; i < 32 * 64; i += 256) {
        const int j = i >> 6, d = i & 63;
        fs[j * 65 + d] = F[(jbase + j) * 64 + d];
    }
    __syncthreads();

    const int j  = tid & 31;
    const int kg = tid >> 5;            // 0..7
    float s = 0.f, s2 = 0.f, sw = 0.f;

    #pragma unroll 4
    for (int kk = 0; kk < 16; kk++) {
        const int k = kg * 16 + kk;
        float a = hb1s[k];
        #pragma unroll
        for (int d = 0; d < 64; d++) a += fs[j * 65 + d] * w1s[d * 128 + k];
        g_FAT[k * 4096 + jbase + j] = a;
        s += a; s2 += a * a; sw += w0s[k] * a;
    }
    redS[kg][j] = s; redS2[kg][j] = s2; redSW[kg][j] = sw;
    __syncthreads();

    if (tid < 32) {
        float S = 0.f, S2 = 0.f, SW = 0.f;
        #pragma unroll
        for (int g = 0; g < 8; g++) {
            S += redS[g][tid]; S2 += redS2[g][tid]; SW += redSW[g][tid];
        }
        const int jj = jbase + tid;
        g_stats[4 * jj + 0] = S  * (1.f / 128.f);
        g_stats[4 * jj + 1] = S2 * (1.f / 128.f);
        g_stats[4 * jj + 2] = SW * (1.f / 128.f);
        g_stats[4 * jj + 3] = 0.f;
    }
}

// ============================================================================
// K1: fused main kernel, 128 threads/block, FFMA2 (fma.rn.f32x2) SGEMM.
// Block = (b, jt): 128 j's for one b.
//   phase1: hT[k][j] = relu(LN1(x*w0 + FA)) via analytic LN stats (float4 path)
//   phase2: 128x64x128 SGEMM, 8j x 8d per thread, accumulators packed along j
//   phase3: LN2 + affine + relu, masked accumulate over j -> g_part[jt][b][:]
// Dynamic smem (floats):
//   [0, 8192)            W2s [k][d] 128x64
//   [8192, +128*132)     hTs [k][j] stride 132 (reused as gs [j][d] stride 67)
//   tail: small per-j arrays
// ============================================================================
#define K1_W2_OFF    0
#define K1_HT_OFF    8192
#define K1_HT_STRIDE 132
#define K1_TAIL      (8192 + 128 * K1_HT_STRIDE)   // 25088
#define K1_SMEM_FLOATS (K1_TAIL + 1360)
#define K1_SMEM_BYTES  (K1_SMEM_FLOATS * 4)

__global__ __launch_bounds__(128) void k1_main(
    const float* __restrict__ x, const int* __restrict__ mask,
    const float* __restrict__ hW1, const float* __restrict__ hg1,
    const float* __restrict__ hbt1, const float* __restrict__ hW2,
    const float* __restrict__ hb2, const float* __restrict__ hg2,
    const float* __restrict__ hbt2)
{
    extern __shared__ float sm[];
    float* W2s  = sm + K1_W2_OFF;
    float* hTs  = sm + K1_HT_OFF;
    float* w0s  = sm + K1_TAIL;            // 128
    float* g1s  = w0s + 128;               // 128
    float* bt1s = g1s + 128;               // 128
    float* b2s  = bt1s + 128;              // 64
    float* g2s  = b2s + 64;                // 64
    float* bt2s = g2s + 64;                // 64
    float* mu_s = bt2s + 64;               // 128
    float* s_s  = mu_s + 128;              // 128
    float* x_s  = s_s + 128;               // 128
    float* wm_s = x_s + 128;               // 128
    float* mu2  = wm_s + 128;              // 128
    float* is2  = mu2 + 128;               // 128
    float* mwvw = is2 + 128;               // 2

    const int tid = threadIdx.x;
    const int b = blockIdx.x;
    const int jt = blockIdx.y;
    const int jbase = jt * 128;

    // setup loads
    w0s[tid] = hW1[tid]; g1s[tid] = hg1[tid]; bt1s[tid] = hbt1[tid];
    if (tid < 64) { b2s[tid] = hb2[tid]; g2s[tid] = hg2[tid]; bt2s[tid] = hbt2[tid]; }
    {
        const float4* src = reinterpret_cast<const float4*>(hW2);
        float4* dst = reinterpret_cast<float4*>(W2s);
        #pragma unroll
        for (int i = 0; i < 16; i++) dst[i * 128 + tid] = src[i * 128 + tid];
    }

    // mean/var of w0 (warp 0)
    if (tid < 32) {
        float s = 0.f, s2 = 0.f;
        #pragma unroll
        for (int kk = 0; kk < 4; kk++) {
            const float w = hW1[kk * 32 + tid];
            s += w; s2 += w * w;
        }
        #pragma unroll
        for (int o = 16; o > 0; o >>= 1) {
            s  += __shfl_xor_sync(0xffffffffu, s,  o);
            s2 += __shfl_xor_sync(0xffffffffu, s2, o);
        }
        if (tid == 0) {
            const float mw = s * (1.f / 128.f);
            mwvw[0] = mw; mwvw[1] = s2 * (1.f / 128.f) - mw * mw;
        }
    }
    __syncthreads();

    // analytic LN1 stats per j
    {
        const int j = jbase + tid;
        const float xv = x[b * 4096 + j];
        const float4 st = *reinterpret_cast<const float4*>(&g_stats[4 * j]);
        const float mw = mwvw[0], vw = mwvw[1];
        const float mu = xv * mw + st.x;
        const float var = xv * xv * vw + 2.f * xv * (st.z - mw * st.x)
                        + (st.y - st.x * st.x);
        mu_s[tid] = mu;
        s_s[tid]  = rsqrtf(var + EPS);
        x_s[tid]  = xv;
        wm_s[tid] = (mask[b * 4096 + j] > 0) ? 1.f : 0.f;
    }
    __syncthreads();

    // phase1: build relu(LN1) tile transposed [k][j], float4 vectorized
    {
        const int g  = tid & 31;       // j4 group
        const int kx = tid >> 5;       // 0..3
        #pragma unroll 4
        for (int p = 0; p < 32; p++) {
            const int k = p * 4 + kx;
            const float4 fa = *reinterpret_cast<const float4*>(g_FAT + k * 4096 + jbase + g * 4);
            const float w0k = w0s[k], g1k = g1s[k], bt1k = bt1s[k];
            const float4 xv = *reinterpret_cast<const float4*>(x_s + g * 4);
            const float4 mu = *reinterpret_cast<const float4*>(mu_s + g * 4);
            const float4 ss = *reinterpret_cast<const float4*>(s_s + g * 4);
            float4 v;
            v.x = fmaxf((w0k * xv.x + fa.x - mu.x) * ss.x * g1k + bt1k, 0.f);
            v.y = fmaxf((w0k * xv.y + fa.y - mu.y) * ss.y * g1k + bt1k, 0.f);
            v.z = fmaxf((w0k * xv.z + fa.z - mu.z) * ss.z * g1k + bt1k, 0.f);
            v.w = fmaxf((w0k * xv.w + fa.w - mu.w) * ss.w * g1k + bt1k, 0.f);
            *reinterpret_cast<float4*>(hTs + k * K1_HT_STRIDE + g * 4) = v;
        }
    }
    __syncthreads();

    // phase2: 128x64x128 SGEMM via FFMA2. 8j x 8d per thread, pairs along j.
    const int tx = tid & 7;        // d-group: 8 d
    const int ty = tid >> 3;       // j-group: 8 j (16 groups)
    unsigned long long acc[4][8];
    #pragma unroll
    for (int jp = 0; jp < 4; jp++)
        #pragma unroll
        for (int dd = 0; dd < 8; dd++) acc[jp][dd] = 0ull;

    const float* aptr = hTs + ty * 8;
    const float* bptr = W2s + tx * 8;

    #pragma unroll 4
    for (int k = 0; k < 128; k++) {
        const ulonglong2 a01 = *reinterpret_cast<const ulonglong2*>(aptr + k * K1_HT_STRIDE);
        const ulonglong2 a23 = *reinterpret_cast<const ulonglong2*>(aptr + k * K1_HT_STRIDE + 4);
        const float4 b0 = *reinterpret_cast<const float4*>(bptr + k * 64);
        const float4 b1 = *reinterpret_cast<const float4*>(bptr + k * 64 + 4);
        const unsigned long long av[4] = {a01.x, a01.y, a23.x, a23.y};
        const unsigned long long bd[8] = {
            pack2(b0.x), pack2(b0.y), pack2(b0.z), pack2(b0.w),
            pack2(b1.x), pack2(b1.y), pack2(b1.z), pack2(b1.w)};
        #pragma unroll
        for (int jp = 0; jp < 4; jp++)
            #pragma unroll
            for (int dd = 0; dd < 8; dd++)
                acc[jp][dd] = ffma2(av[jp], bd[dd], acc[jp][dd]);
    }
    __syncthreads();   // all reads of hTs done; reuse as gs

    // epilogue: g = acc + hb2 into gs [j][d] stride 67
    float* gs = hTs;
    #pragma unroll
    for (int jp = 0; jp < 4; jp++) {
        const int j0 = ty * 8 + jp * 2;
        #pragma unroll
        for (int dd = 0; dd < 8; dd++) {
            const int d = tx * 8 + dd;
            float lo, hi;
            unpack2(acc[jp][dd], lo, hi);
            gs[j0 * 67 + d]       = lo + b2s[d];
            gs[(j0 + 1) * 67 + d] = hi + b2s[d];
        }
    }
    __syncthreads();

    // LN2 stats per row
    {
        float s = 0.f, s2 = 0.f;
        #pragma unroll 8
        for (int d = 0; d < 64; d++) { const float g = gs[tid * 67 + d]; s += g; s2 += g * g; }
        const float mu = s * (1.f / 64.f);
        const float var = s2 * (1.f / 64.f) - mu * mu;
        mu2[tid] = mu;
        is2[tid] = rsqrtf(var + EPS);
    }
    __syncthreads();

    // masked pool over the 128 j's
    if (tid < 64) {
        float a = 0.f;
        #pragma unroll 8
        for (int j = 0; j < 128; j++) {
            const float v = (gs[j * 67 + tid] - mu2[j]) * is2[j] * g2s[tid] + bt2s[tid];
            a += wm_s[j] * fmaxf(v, 0.f);
        }
        g_part[(jt * 128 + b) * 64 + tid] = a;
    }
}

// ============================================================================
// K2: per-b reduction + head MLP. 128 blocks x 256 threads.
// ============================================================================
__global__ __launch_bounds__(256) void k2_head(
    const int* __restrict__ mask,
    const float* __restrict__ eW1, const float* __restrict__ eb1,
    const float* __restrict__ eW2, const float* __restrict__ eb2,
    float* __restrict__ out)
{
    __shared__ float c_s[64];
    __shared__ float e_s[256];
    __shared__ float red[16];
    __shared__ int   redi[8];
    __shared__ float os[64];
    __shared__ float sc[4];

    const int b = blockIdx.x;
    const int tid = threadIdx.x;

    // observed count
    int cnt = 0;
    for (int i = tid; i < 4096; i += 256) cnt += (mask[b * 4096 + i] > 0);
    #pragma unroll
    for (int o = 16; o > 0; o >>= 1) cnt += __shfl_xor_sync(0xffffffffu, cnt, o);
    if ((tid & 31) == 0) redi[tid >> 5] = cnt;

    // pooled partial reduction (deterministic fixed order)
    float s = 0.f;
    if (tid < 64) {
        #pragma unroll
        for (int jt = 0; jt < 32; jt++) s += g_part[(jt * 128 + b) * 64 + tid];
    }
    __syncthreads();
    if (tid == 0) {
        int c = 0;
        #pragma unroll
        for (int w = 0; w < 8; w++) c += redi[w];
        sc[0] = fmaxf((float)c, 1.f);
    }
    __syncthreads();
    if (tid < 64) c_s[tid] = s / sc[0];
    __syncthreads();

    // e = relu(LN_na(c @ eW1 + eb1)), E = 256
    float t = eb1[tid];
    #pragma unroll 4
    for (int d = 0; d < 64; d++) t += c_s[d] * eW1[d * 256 + tid];
    {
        float s1 = t, s2 = t * t;
        #pragma unroll
        for (int o = 16; o > 0; o >>= 1) {
            s1 += __shfl_xor_sync(0xffffffffu, s1, o);
            s2 += __shfl_xor_sync(0xffffffffu, s2, o);
        }
        if ((tid & 31) == 0) { red[tid >> 5] = s1; red[8 + (tid >> 5)] = s2; }
        __syncthreads();
        if (tid == 0) {
            float S1 = 0.f, S2 = 0.f;
            #pragma unroll
            for (int w = 0; w < 8; w++) { S1 += red[w]; S2 += red[8 + w]; }
            const float mu = S1 * (1.f / 256.f);
            const float var = S2 * (1.f / 256.f) - mu * mu;
            sc[1] = mu; sc[2] = rsqrtf(var + EPS);
        }
        __syncthreads();
    }
    e_s[tid] = fmaxf(0.f, (t - sc[1]) * sc[2]);
    __syncthreads();

    // out = relu(LN_na(e @ eW2 + eb2)), 64 outputs
    if (tid < 64) {
        float o = eb2[tid];
        #pragma unroll 4
        for (int i = 0; i < 256; i++) o += e_s[i] * eW2[i * 64 + tid];
        os[tid] = o;
    }
    __syncthreads();
    if (tid < 32) {
        const float a = os[tid], c = os[tid + 32];
        float s1 = a + c, s2 = a * a + c * c;
        #pragma unroll
        for (int o = 16; o > 0; o >>= 1) {
            s1 += __shfl_xor_sync(0xffffffffu, s1, o);
            s2 += __shfl_xor_sync(0xffffffffu, s2, o);
        }
        if (tid == 0) {
            const float mu = s1 * (1.f / 64.f);
            const float var = s2 * (1.f / 64.f) - mu * mu;
            sc[1] = mu; sc[2] = rsqrtf(var + EPS);
        }
    }
    __syncthreads();
    if (tid < 64) {
        const float v = fmaxf(0.f, (os[tid] - sc[1]) * sc[2]);
        if (tid < 32) out[b * 32 + tid] = v;                   // mu
        else          out[128 * 32 + b * 32 + (tid - 32)] = v; // logvar
    }
}

// ============================================================================
extern "C" void kernel_launch(void* const* d_in, const int* in_sizes, int n_in,
                              void* d_out, int out_size)
{
    const float* x    = (const float*)d_in[0];
    const int*   mask = (const int*)  d_in[1];
    const float* F    = (const float*)d_in[2];
    const float* hW1  = (const float*)d_in[3];
    const float* hb1  = (const float*)d_in[4];
    const float* hg1  = (const float*)d_in[5];
    const float* hbt1 = (const float*)d_in[6];
    const float* hW2  = (const float*)d_in[7];
    const float* hb2  = (const float*)d_in[8];
    const float* hg2  = (const float*)d_in[9];
    const float* hbt2 = (const float*)d_in[10];
    const float* eW1  = (const float*)d_in[11];
    const float* eb1  = (const float*)d_in[12];
    const float* eW2  = (const float*)d_in[13];
    const float* eb2  = (const float*)d_in[14];
    float* out = (float*)d_out;

    cudaFuncSetAttribute(k1_main, cudaFuncAttributeMaxDynamicSharedMemorySize,
                         K1_SMEM_BYTES);

    k0_precompute<<<128, 256>>>(F, hW1, hb1);
    dim3 g1(128, 32);
    k1_main<<<g1, 128, K1_SMEM_BYTES>>>(x, mask, hW1, hg1, hbt1, hW2,
                                        hb2, hg2, hbt2);
    k2_head<<<128, 256>>>(mask, eW1, eb1, eW2, eb2, out);
}

// round 8
// speedup vs baseline: 1.4769x; 1.1833x over previous
#include <cuda_runtime.h>
#include <cuda_bf16.h>
#include <cstdint>

// ---------------- scratch (static device globals; no allocation) ----------------
__device__ float g_FAT[4096 * 128];     // [j][k] : FA = F @ hW1[1:] + hb1, 2 MB
__device__ float g_stats[4096 * 4];     // per j: ma, m2a, mwa, pad
__device__ float g_part[32 * 128 * 64]; // [jt][b][d] partial masked pools, 1 MB
__device__ uint4 g_Bh[1024];            // W2^T bf16 hi, [d][k] plain rows (16KB)
__device__ uint4 g_Bl[1024];            // W2^T bf16 lo residual (16KB)

#define EPS 1e-5f

// ---------------- PTX helpers ----------------
__device__ __forceinline__ uint32_t smem_to_u32(const void* p) {
    uint32_t a;
    asm("{ .reg .u64 t; cvta.to.shared.u64 t, %1; cvt.u32.u64 %0, t; }"
        : "=r"(a) : "l"(p));
    return a;
}
__device__ __forceinline__ void ldsm4(uint32_t* r, uint32_t addr) {
    asm volatile("ldmatrix.sync.aligned.m8n8.x4.shared.b16 {%0,%1,%2,%3}, [%4];"
        : "=r"(r[0]), "=r"(r[1]), "=r"(r[2]), "=r"(r[3]) : "r"(addr));
}
__device__ __forceinline__ void mma_bf16(float* c, const uint32_t* a,
                                         uint32_t b0, uint32_t b1) {
    asm volatile(
        "mma.sync.aligned.m16n8k16.row.col.f32.bf16.bf16.f32 "
        "{%0,%1,%2,%3}, {%4,%5,%6,%7}, {%8,%9}, {%0,%1,%2,%3};"
        : "+f"(c[0]), "+f"(c[1]), "+f"(c[2]), "+f"(c[3])
        : "r"(a[0]), "r"(a[1]), "r"(a[2]), "r"(a[3]), "r"(b0), "r"(b1));
}
#define CVT_BF16X2_F32(result, a, b) \
    asm("cvt.rn.satfinite.bf16x2.f32 %0, %1, %2;" : "=r"(result) : "f"(b), "f"(a))

// ============================================================================
// K0: FA[j][k] = hb1[k] + sum_d F[j][d] * hW1[1+d][k], stored [j][k], plus
// per-j stats (ma, m2a, mwa). 256 blocks x 256 thr; block = 16 j.
// Thread (kg = tid>>4 [0..15], j = tid&15) computes 8 k's.
// ============================================================================
__global__ __launch_bounds__(256) void k0_precompute(
    const float* __restrict__ F, const float* __restrict__ hW1,
    const float* __restrict__ hb1)
{
    __shared__ float w1t[128 * 68];     // [k][d] stride 68
    __shared__ float fs[16 * 68];       // [j][d] stride 68
    __shared__ float w0s[128];
    __shared__ float hb1s[128];
    __shared__ float rS[16][17], rS2[16][17], rSW[16][17];

    const int tid = threadIdx.x;
    const int jbase = blockIdx.x * 16;

    for (int i = tid; i < 64 * 128; i += 256) {
        const int d = i >> 7, k = i & 127;
        w1t[k * 68 + d] = hW1[128 + i];
    }
    if (tid < 128) { w0s[tid] = hW1[tid]; hb1s[tid] = hb1[tid]; }
    for (int i = tid; i < 16 * 64; i += 256) {
        const int j = i >> 6, d = i & 63;
        fs[j * 68 + d] = F[(jbase + j) * 64 + d];
    }
    __syncthreads();

    const int kg = tid >> 4;            // 0..15, 8 k's each
    const int j  = tid & 15;            // 0..15
    float acc[8];
    #pragma unroll
    for (int kk = 0; kk < 8; kk++) acc[kk] = hb1s[kg * 8 + kk];

    #pragma unroll
    for (int d4 = 0; d4 < 16; d4++) {
        const float4 f = *reinterpret_cast<const float4*>(&fs[j * 68 + d4 * 4]);
        #pragma unroll
        for (int kk = 0; kk < 8; kk++) {
            const int k = kg * 8 + kk;
            const float4 w = *reinterpret_cast<const float4*>(&w1t[k * 68 + d4 * 4]);
            acc[kk] += f.x * w.x + f.y * w.y + f.z * w.z + f.w * w.w;
        }
    }

    float s = 0.f, s2 = 0.f, sw = 0.f;
    #pragma unroll
    for (int kk = 0; kk < 8; kk++) {
        const float a = acc[kk];
        s += a; s2 += a * a; sw += w0s[kg * 8 + kk] * a;
    }
    float* dst = g_FAT + (jbase + j) * 128 + kg * 8;
    *reinterpret_cast<float4*>(dst)     = make_float4(acc[0], acc[1], acc[2], acc[3]);
    *reinterpret_cast<float4*>(dst + 4) = make_float4(acc[4], acc[5], acc[6], acc[7]);
    rS[j][kg] = s; rS2[j][kg] = s2; rSW[j][kg] = sw;
    __syncthreads();

    if (tid < 16) {
        float S = 0.f, S2 = 0.f, SW = 0.f;
        #pragma unroll
        for (int g = 0; g < 16; g++) {
            S += rS[tid][g]; S2 += rS2[tid][g]; SW += rSW[tid][g];
        }
        const int jj = jbase + tid;
        g_stats[4 * jj + 0] = S  * (1.f / 128.f);
        g_stats[4 * jj + 1] = S2 * (1.f / 128.f);
        g_stats[4 * jj + 2] = SW * (1.f / 128.f);
        g_stats[4 * jj + 3] = 0.f;
    }
}

// ============================================================================
// K0b: split W2 (128k x 64d) into bf16 hi/lo, stored as B[d][k] plain rows
// (d rows, k contiguous, 256B per row) -> ldmatrix-ready after padded copy.
// ============================================================================
__global__ __launch_bounds__(256) void k0b_prepB(const float* __restrict__ hW2)
{
    const int idx = blockIdx.x * 256 + threadIdx.x;   // 8192 elems
    if (idx >= 8192) return;
    const int k = idx >> 6, d = idx & 63;
    const float v = hW2[idx];                          // W2[k][d]
    const __nv_bfloat16 hi = __float2bfloat16(v);
    const float hif = __bfloat162float(hi);
    const __nv_bfloat16 lo = __float2bfloat16(v - hif);
    reinterpret_cast<__nv_bfloat16*>(g_Bh)[d * 128 + k] = hi;
    reinterpret_cast<__nv_bfloat16*>(g_Bl)[d * 128 + k] = lo;
}

// ============================================================================
// K1: persistent fused kernel, mma.sync bf16 3-term split GEMM (HMMA).
// Grid (8 bgroups, 32 jt), 256 threads (8 warps). Block: one jt x 16 b's.
// Warp layout: jw = wid>>1 (4 x 32j), dw = wid&1 (2 x 32d); frags jm=2, dn=4.
// Per b: phase1 builds A=relu(LN1) as bf16 hi/lo planes [j][k] (272B rows);
// mainloop: 8 k16-steps of ldmatrix + 24 mma (hh, hl, lh) into reg acc;
// epilogue: +hb2 -> gs smem, LN2 + affine + relu + masked pool -> g_part.
//
// SMEM (bytes): A_hi[0,34816) A_lo[34816,69632) B_hi[69632,87040)
//               B_lo[87040,104448) tail[104448,...). gs reuses A_hi (stride 66 f).
// ============================================================================
#define A_HI_OFF   0
#define A_LO_OFF   34816
#define B_HI_OFF   69632
#define B_LO_OFF   87040
#define TAIL_OFF   104448
#define C4S_OFF    (TAIL_OFF)            // float4[128] = 2048
#define B2S_OFF    (TAIL_OFF + 2048)
#define G2S_OFF    (TAIL_OFF + 2304)
#define BT2S_OFF   (TAIL_OFF + 2560)
#define XS_OFF     (TAIL_OFF + 2816)
#define SS_OFF     (TAIL_OFF + 3328)
#define MS_OFF     (TAIL_OFF + 3840)
#define WM_OFF     (TAIL_OFF + 4352)
#define MU2_OFF    (TAIL_OFF + 4864)
#define IS2_OFF    (TAIL_OFF + 5376)
#define MWVW_OFF   (TAIL_OFF + 5888)
#define K1_SMEM_BYTES 110592

__global__ __launch_bounds__(256, 2) void k1_main(
    const float* __restrict__ x, const int* __restrict__ mask,
    const float* __restrict__ hW1, const float* __restrict__ hg1,
    const float* __restrict__ hbt1,
    const float* __restrict__ hb2, const float* __restrict__ hg2,
    const float* __restrict__ hbt2)
{
    extern __shared__ char smem[];
    const uint32_t smem_u32 = smem_to_u32(smem);

    float4* c4s  = reinterpret_cast<float4*>(smem + C4S_OFF);
    float*  b2s  = reinterpret_cast<float*>(smem + B2S_OFF);
    float*  g2s  = reinterpret_cast<float*>(smem + G2S_OFF);
    float*  bt2s = reinterpret_cast<float*>(smem + BT2S_OFF);
    float*  xs_s = reinterpret_cast<float*>(smem + XS_OFF);
    float*  s_s  = reinterpret_cast<float*>(smem + SS_OFF);
    float*  ms_s = reinterpret_cast<float*>(smem + MS_OFF);
    float*  wm_s = reinterpret_cast<float*>(smem + WM_OFF);
    float*  mu2  = reinterpret_cast<float*>(smem + MU2_OFF);
    float*  is2  = reinterpret_cast<float*>(smem + IS2_OFF);
    float*  mwvw = reinterpret_cast<float*>(smem + MWVW_OFF);
    float*  gs   = reinterpret_cast<float*>(smem);   // stride 66, reuses A_hi

    const int tid = threadIdx.x;
    const int wid = tid >> 5;
    const int lid = tid & 31;
    const int jt = blockIdx.y;
    const int jbase = jt * 128;

    // ---- one-time setup ----
    {   // B planes: copy [d][k] rows (256B) into padded 272B rows
        const uint4* sh = g_Bh;
        const uint4* sl = g_Bl;
        #pragma unroll
        for (int it = 0; it < 4; it++) {
            const int i = it * 256 + tid;
            const int row = i >> 4, c = i & 15;
            *reinterpret_cast<uint4*>(smem + B_HI_OFF + row * 272 + c * 16) = sh[i];
            *reinterpret_cast<uint4*>(smem + B_LO_OFF + row * 272 + c * 16) = sl[i];
        }
    }
    if (tid < 128) {
        const float g1v = hg1[tid];
        c4s[tid] = make_float4(hW1[tid] * g1v, g1v, hbt1[tid], 0.f);
    } else if (tid < 192) {
        const int t = tid - 128;
        b2s[t] = hb2[t]; g2s[t] = hg2[t]; bt2s[t] = hbt2[t];
    } else if (tid < 224) {
        const int l = tid - 192;
        float s = 0.f, s2 = 0.f;
        #pragma unroll
        for (int kk = 0; kk < 4; kk++) { const float w = hW1[kk * 32 + l]; s += w; s2 += w * w; }
        #pragma unroll
        for (int o = 16; o > 0; o >>= 1) {
            s  += __shfl_xor_sync(0xffffffffu, s,  o);
            s2 += __shfl_xor_sync(0xffffffffu, s2, o);
        }
        if (l == 0) {
            const float mw = s * (1.f / 128.f);
            mwvw[0] = mw; mwvw[1] = s2 * (1.f / 128.f) - mw * mw;
        }
    }
    __syncthreads();

    // mainloop thread geometry
    const int jw = wid >> 1;          // 0..3 : j-block of 32
    const int dw = wid & 1;           // 0..1 : d-block of 32
    const int g  = lid >> 2;          // 0..7
    const int t  = lid & 3;           // 0..3
    const uint32_t a_base = smem_u32 + A_HI_OFF
        + (uint32_t)((jw * 32 + (lid & 15)) * 272 + (lid >> 4) * 16);
    const uint32_t b_base = smem_u32 + B_HI_OFF
        + (uint32_t)((dw * 32 + (lid >> 4) * 8 + (lid & 7)) * 272
                     + ((lid >> 3) & 1) * 16);

    // phase1 geometry
    const int pj = tid & 127;
    const int kh = tid >> 7;
    const uint32_t a_st = (uint32_t)(pj * 272 + kh * 128);

    for (int bb = 0; bb < 16; bb++) {
        const int b = blockIdx.x * 16 + bb;

        // ---- per-j analytic LN1 stats ----
        if (tid < 128) {
            const int j = jbase + tid;
            const float xv = x[b * 4096 + j];
            const float4 st = *reinterpret_cast<const float4*>(&g_stats[4 * j]);
            const float mw = mwvw[0], vw = mwvw[1];
            const float mu = xv * mw + st.x;
            const float var = xv * xv * vw + 2.f * xv * (st.z - mw * st.x)
                            + (st.y - st.x * st.x);
            const float s = rsqrtf(var + EPS);
            xs_s[tid] = xv * s;
            s_s[tid]  = s;
            ms_s[tid] = mu * s;
            wm_s[tid] = (mask[b * 4096 + j] > 0) ? 1.f : 0.f;
        }
        __syncthreads();

        // ---- phase1: A = relu(LN1) bf16 hi/lo planes, [j][k] rows 272B ----
        {
            const float sj = s_s[pj], xsv = xs_s[pj], msv = ms_s[pj];
            const float4* fat = reinterpret_cast<const float4*>(
                g_FAT + (jbase + pj) * 128 + kh * 64);
            #pragma unroll
            for (int gg = 0; gg < 8; gg++) {
                const float4 fa0 = fat[gg * 2];
                const float4 fa1 = fat[gg * 2 + 1];
                const float fav[8] = {fa0.x, fa0.y, fa0.z, fa0.w,
                                      fa1.x, fa1.y, fa1.z, fa1.w};
                float v[8];
                #pragma unroll
                for (int kk = 0; kk < 8; kk++) {
                    const float4 c = c4s[kh * 64 + gg * 8 + kk];
                    const float base = fmaf(c.x, xsv, fmaf(c.y, -msv, c.z));
                    v[kk] = fmaxf(fmaf(c.y * sj, fav[kk], base), 0.f);
                }
                uint32_t p[4], q[4];
                #pragma unroll
                for (int u = 0; u < 4; u++) {
                    CVT_BF16X2_F32(p[u], v[2 * u], v[2 * u + 1]);
                    const float f0 = __uint_as_float(p[u] << 16);
                    const float f1 = __uint_as_float(p[u] & 0xffff0000u);
                    CVT_BF16X2_F32(q[u], v[2 * u] - f0, v[2 * u + 1] - f1);
                }
                const uint32_t off = a_st + gg * 16;
                *reinterpret_cast<uint4*>(smem + A_HI_OFF + off) = make_uint4(p[0], p[1], p[2], p[3]);
                *reinterpret_cast<uint4*>(smem + A_LO_OFF + off) = make_uint4(q[0], q[1], q[2], q[3]);
            }
        }
        __syncthreads();

        // ---- mainloop: 8 k16-steps, 3-term bf16 mma ----
        float acc[2][4][4];
        #pragma unroll
        for (int jm = 0; jm < 2; jm++)
            #pragma unroll
            for (int dn = 0; dn < 4; dn++)
                #pragma unroll
                for (int r = 0; r < 4; r++) acc[jm][dn][r] = 0.f;

        #pragma unroll
        for (int ks = 0; ks < 8; ks++) {
            const uint32_t kb = ks * 32;
            uint32_t ah[2][4], al[2][4], bh[4][2], bl[4][2];
            ldsm4(ah[0], a_base + kb);
            ldsm4(ah[1], a_base + 16 * 272 + kb);
            ldsm4(al[0], a_base + (A_LO_OFF - A_HI_OFF) + kb);
            ldsm4(al[1], a_base + (A_LO_OFF - A_HI_OFF) + 16 * 272 + kb);
            ldsm4(&bh[0][0], b_base + kb);
            ldsm4(&bh[2][0], b_base + 16 * 272 + kb);
            ldsm4(&bl[0][0], b_base + (B_LO_OFF - B_HI_OFF) + kb);
            ldsm4(&bl[2][0], b_base + (B_LO_OFF - B_HI_OFF) + 16 * 272 + kb);
            #pragma unroll
            for (int jm = 0; jm < 2; jm++)
                #pragma unroll
                for (int dn = 0; dn < 4; dn++) {
                    mma_bf16(acc[jm][dn], ah[jm], bh[dn][0], bh[dn][1]);
                    mma_bf16(acc[jm][dn], ah[jm], bl[dn][0], bl[dn][1]);
                    mma_bf16(acc[jm][dn], al[jm], bh[dn][0], bh[dn][1]);
                }
        }
        __syncthreads();   // A reads done; reuse A_hi region as gs

        // ---- epilogue: +hb2 -> gs [j][d] stride 66 ----
        #pragma unroll
        for (int jm = 0; jm < 2; jm++) {
            const int j0 = jw * 32 + jm * 16 + g;
            #pragma unroll
            for (int dn = 0; dn < 4; dn++) {
                const int d = dw * 32 + dn * 8 + t * 2;
                const float* c = acc[jm][dn];
                gs[j0 * 66 + d]           = c[0] + b2s[d];
                gs[j0 * 66 + d + 1]       = c[1] + b2s[d + 1];
                gs[(j0 + 8) * 66 + d]     = c[2] + b2s[d];
                gs[(j0 + 8) * 66 + d + 1] = c[3] + b2s[d + 1];
            }
        }
        __syncthreads();

        // ---- LN2 stats per row ----
        if (tid < 128) {
            float s = 0.f, s2 = 0.f;
            #pragma unroll 8
            for (int d = 0; d < 64; d++) { const float v = gs[tid * 66 + d]; s += v; s2 += v * v; }
            const float mu = s * (1.f / 64.f);
            const float var = s2 * (1.f / 64.f) - mu * mu;
            mu2[tid] = mu;
            is2[tid] = rsqrtf(var + EPS);
        }
        __syncthreads();

        // ---- masked pool over 128 j ----
        if (tid < 64) {
            float a = 0.f;
            #pragma unroll 8
            for (int j = 0; j < 128; j++) {
                const float v = (gs[j * 66 + tid] - mu2[j]) * is2[j] * g2s[tid] + bt2s[tid];
                a += wm_s[j] * fmaxf(v, 0.f);
            }
            g_part[(jt * 128 + b) * 64 + tid] = a;
        }
        __syncthreads();
    }
}

// ============================================================================
// K2: per-b reduction + head MLP. 128 blocks x 256 threads.
// ============================================================================
__global__ __launch_bounds__(256) void k2_head(
    const int* __restrict__ mask,
    const float* __restrict__ eW1, const float* __restrict__ eb1,
    const float* __restrict__ eW2, const float* __restrict__ eb2,
    float* __restrict__ out)
{
    __shared__ float c_s[64];
    __shared__ float e_s[256];
    __shared__ float red[16];
    __shared__ int   redi[8];
    __shared__ float os[64];
    __shared__ float sc[4];

    const int b = blockIdx.x;
    const int tid = threadIdx.x;

    int cnt = 0;
    for (int i = tid; i < 4096; i += 256) cnt += (mask[b * 4096 + i] > 0);
    #pragma unroll
    for (int o = 16; o > 0; o >>= 1) cnt += __shfl_xor_sync(0xffffffffu, cnt, o);
    if ((tid & 31) == 0) redi[tid >> 5] = cnt;

    float s = 0.f;
    if (tid < 64) {
        #pragma unroll
        for (int jt = 0; jt < 32; jt++) s += g_part[(jt * 128 + b) * 64 + tid];
    }
    __syncthreads();
    if (tid == 0) {
        int c = 0;
        #pragma unroll
        for (int w = 0; w < 8; w++) c += redi[w];
        sc[0] = fmaxf((float)c, 1.f);
    }
    __syncthreads();
    if (tid < 64) c_s[tid] = s / sc[0];
    __syncthreads();

    float t = eb1[tid];
    #pragma unroll 4
    for (int d = 0; d < 64; d++) t += c_s[d] * eW1[d * 256 + tid];
    {
        float s1 = t, s2 = t * t;
        #pragma unroll
        for (int o = 16; o > 0; o >>= 1) {
            s1 += __shfl_xor_sync(0xffffffffu, s1, o);
            s2 += __shfl_xor_sync(0xffffffffu, s2, o);
        }
        if ((tid & 31) == 0) { red[tid >> 5] = s1; red[8 + (tid >> 5)] = s2; }
        __syncthreads();
        if (tid == 0) {
            float S1 = 0.f, S2 = 0.f;
            #pragma unroll
            for (int w = 0; w < 8; w++) { S1 += red[w]; S2 += red[8 + w]; }
            const float mu = S1 * (1.f / 256.f);
            const float var = S2 * (1.f / 256.f) - mu * mu;
            sc[1] = mu; sc[2] = rsqrtf(var + EPS);
        }
        __syncthreads();
    }
    e_s[tid] = fmaxf(0.f, (t - sc[1]) * sc[2]);
    __syncthreads();

    if (tid < 64) {
        float o = eb2[tid];
        #pragma unroll 4
        for (int i = 0; i < 256; i++) o += e_s[i] * eW2[i * 64 + tid];
        os[tid] = o;
    }
    __syncthreads();
    if (tid < 32) {
        const float a = os[tid], c = os[tid + 32];
        float s1 = a + c, s2 = a * a + c * c;
        #pragma unroll
        for (int o = 16; o > 0; o >>= 1) {
            s1 += __shfl_xor_sync(0xffffffffu, s1, o);
            s2 += __shfl_xor_sync(0xffffffffu, s2, o);
        }
        if (tid == 0) {
            const float mu = s1 * (1.f / 64.f);
            const float var = s2 * (1.f / 64.f) - mu * mu;
            sc[1] = mu; sc[2] = rsqrtf(var + EPS);
        }
    }
    __syncthreads();
    if (tid < 64) {
        const float v = fmaxf(0.f, (os[tid] - sc[1]) * sc[2]);
        if (tid < 32) out[b * 32 + tid] = v;                   // mu
        else          out[128 * 32 + b * 32 + (tid - 32)] = v; // logvar
    }
}

// ============================================================================
extern "C" void kernel_launch(void* const* d_in, const int* in_sizes, int n_in,
                              void* d_out, int out_size)
{
    const float* x    = (const float*)d_in[0];
    const int*   mask = (const int*)  d_in[1];
    const float* F    = (const float*)d_in[2];
    const float* hW1  = (const float*)d_in[3];
    const float* hb1  = (const float*)d_in[4];
    const float* hg1  = (const float*)d_in[5];
    const float* hbt1 = (const float*)d_in[6];
    const float* hW2  = (const float*)d_in[7];
    const float* hb2  = (const float*)d_in[8];
    const float* hg2  = (const float*)d_in[9];
    const float* hbt2 = (const float*)d_in[10];
    const float* eW1  = (const float*)d_in[11];
    const float* eb1  = (const float*)d_in[12];
    const float* eW2  = (const float*)d_in[13];
    const float* eb2  = (const float*)d_in[14];
    float* out = (float*)d_out;

    cudaFuncSetAttribute(k1_main, cudaFuncAttributeMaxDynamicSharedMemorySize,
                         K1_SMEM_BYTES);

    k0_precompute<<<256, 256>>>(F, hW1, hb1);
    k0b_prepB<<<32, 256>>>(hW2);
    dim3 g1(8, 32);
    k1_main<<<g1, 256, K1_SMEM_BYTES>>>(x, mask, hW1, hg1, hbt1,
                                        hb2, hg2, hbt2);
    k2_head<<<128, 256>>>(mask, eW1, eb1, eW2, eb2, out);
}

// round 11
// speedup vs baseline: 1.5636x; 1.0587x over previous
#include <cuda_runtime.h>
#include <cuda_bf16.h>
#include <cstdint>

// ---------------- scratch (static device globals; no allocation) ----------------
__device__ float g_FAT[4096 * 128];     // [j][k] : FA = F @ hW1[1:] + hb1, 2 MB
__device__ float g_stats[4096 * 4];     // per j: ma, m2a, mwa, pad
__device__ float g_part[32 * 128 * 64]; // [jt][b][d] partial masked pools, 1 MB
__device__ float g_cnt[32 * 128];       // [jt][b] partial observed counts
__device__ uint4 g_Bh[1024];            // W2^T bf16 hi, [d][k] plain rows (16KB)
__device__ uint4 g_Bl[1024];            // W2^T bf16 lo residual (16KB)

#define EPS 1e-5f

// ---------------- PTX helpers ----------------
__device__ __forceinline__ uint32_t smem_to_u32(const void* p) {
    uint32_t a;
    asm("{ .reg .u64 t; cvta.to.shared.u64 t, %1; cvt.u32.u64 %0, t; }"
        : "=r"(a) : "l"(p));
    return a;
}
__device__ __forceinline__ void ldsm4(uint32_t* r, uint32_t addr) {
    asm volatile("ldmatrix.sync.aligned.m8n8.x4.shared.b16 {%0,%1,%2,%3}, [%4];"
        : "=r"(r[0]), "=r"(r[1]), "=r"(r[2]), "=r"(r[3]) : "r"(addr));
}
__device__ __forceinline__ void mma_bf16(float* c, const uint32_t* a,
                                         uint32_t b0, uint32_t b1) {
    asm volatile(
        "mma.sync.aligned.m16n8k16.row.col.f32.bf16.bf16.f32 "
        "{%0,%1,%2,%3}, {%4,%5,%6,%7}, {%8,%9}, {%0,%1,%2,%3};"
        : "+f"(c[0]), "+f"(c[1]), "+f"(c[2]), "+f"(c[3])
        : "r"(a[0]), "r"(a[1]), "r"(a[2]), "r"(a[3]), "r"(b0), "r"(b1));
}
#define CVT_BF16X2_F32(result, a, b) \
    asm("cvt.rn.satfinite.bf16x2.f32 %0, %1, %2;" : "=r"(result) : "f"(b), "f"(a))

// ============================================================================
// K0: FA[j][k] = hb1[k] + sum_d F[j][d] * hW1[1+d][k], stored [j][k], plus
// per-j stats (ma, m2a, mwa). 256 blocks x 256 thr; block = 16 j.
// ============================================================================
__global__ __launch_bounds__(256) void k0_precompute(
    const float* __restrict__ F, const float* __restrict__ hW1,
    const float* __restrict__ hb1)
{
    __shared__ float w1t[128 * 68];     // [k][d] stride 68
    __shared__ float fs[16 * 68];       // [j][d] stride 68
    __shared__ float w0s[128];
    __shared__ float hb1s[128];
    __shared__ float rS[16][17], rS2[16][17], rSW[16][17];

    const int tid = threadIdx.x;
    const int jbase = blockIdx.x * 16;

    for (int i = tid; i < 64 * 128; i += 256) {
        const int d = i >> 7, k = i & 127;
        w1t[k * 68 + d] = hW1[128 + i];
    }
    if (tid < 128) { w0s[tid] = hW1[tid]; hb1s[tid] = hb1[tid]; }
    for (int i = tid; i < 16 * 64; i += 256) {
        const int j = i >> 6, d = i & 63;
        fs[j * 68 + d] = F[(jbase + j) * 64 + d];
    }
    __syncthreads();

    const int kg = tid >> 4;            // 0..15, 8 k's each
    const int j  = tid & 15;            // 0..15
    float acc[8];
    #pragma unroll
    for (int kk = 0; kk < 8; kk++) acc[kk] = hb1s[kg * 8 + kk];

    #pragma unroll
    for (int d4 = 0; d4 < 16; d4++) {
        const float4 f = *reinterpret_cast<const float4*>(&fs[j * 68 + d4 * 4]);
        #pragma unroll
        for (int kk = 0; kk < 8; kk++) {
            const int k = kg * 8 + kk;
            const float4 w = *reinterpret_cast<const float4*>(&w1t[k * 68 + d4 * 4]);
            acc[kk] += f.x * w.x + f.y * w.y + f.z * w.z + f.w * w.w;
        }
    }

    float s = 0.f, s2 = 0.f, sw = 0.f;
    #pragma unroll
    for (int kk = 0; kk < 8; kk++) {
        const float a = acc[kk];
        s += a; s2 += a * a; sw += w0s[kg * 8 + kk] * a;
    }
    float* dst = g_FAT + (jbase + j) * 128 + kg * 8;
    *reinterpret_cast<float4*>(dst)     = make_float4(acc[0], acc[1], acc[2], acc[3]);
    *reinterpret_cast<float4*>(dst + 4) = make_float4(acc[4], acc[5], acc[6], acc[7]);
    rS[j][kg] = s; rS2[j][kg] = s2; rSW[j][kg] = sw;
    __syncthreads();

    if (tid < 16) {
        float S = 0.f, S2 = 0.f, SW = 0.f;
        #pragma unroll
        for (int g = 0; g < 16; g++) {
            S += rS[tid][g]; S2 += rS2[tid][g]; SW += rSW[tid][g];
        }
        const int jj = jbase + tid;
        g_stats[4 * jj + 0] = S  * (1.f / 128.f);
        g_stats[4 * jj + 1] = S2 * (1.f / 128.f);
        g_stats[4 * jj + 2] = SW * (1.f / 128.f);
        g_stats[4 * jj + 3] = 0.f;
    }
}

// ============================================================================
// K0b: split W2 (128k x 64d) into bf16 hi/lo, stored as B[d][k] plain rows.
// ============================================================================
__global__ __launch_bounds__(256) void k0b_prepB(const float* __restrict__ hW2)
{
    const int idx = blockIdx.x * 256 + threadIdx.x;   // 8192 elems
    if (idx >= 8192) return;
    const int k = idx >> 6, d = idx & 63;
    const float v = hW2[idx];                          // W2[k][d]
    const __nv_bfloat16 hi = __float2bfloat16(v);
    const float hif = __bfloat162float(hi);
    const __nv_bfloat16 lo = __float2bfloat16(v - hif);
    reinterpret_cast<__nv_bfloat16*>(g_Bh)[d * 128 + k] = hi;
    reinterpret_cast<__nv_bfloat16*>(g_Bl)[d * 128 + k] = lo;
}

// ============================================================================
// K1: persistent fused kernel, mma.sync bf16 3-term split GEMM (HMMA).
// Grid (8 bgroups, 32 jt), 256 threads (8 warps). Block: one jt x 16 b's.
// Also writes g_cnt[jt][b] = sum of mask (fused; warp 2 during pool phase).
// ============================================================================
#define A_HI_OFF   0
#define A_LO_OFF   34816
#define B_HI_OFF   69632
#define B_LO_OFF   87040
#define TAIL_OFF   104448
#define C4S_OFF    (TAIL_OFF)            // float4[128] = 2048
#define B2S_OFF    (TAIL_OFF + 2048)
#define G2S_OFF    (TAIL_OFF + 2304)
#define BT2S_OFF   (TAIL_OFF + 2560)
#define XS_OFF     (TAIL_OFF + 2816)
#define SS_OFF     (TAIL_OFF + 3328)
#define MS_OFF     (TAIL_OFF + 3840)
#define WM_OFF     (TAIL_OFF + 4352)
#define MU2_OFF    (TAIL_OFF + 4864)
#define IS2_OFF    (TAIL_OFF + 5376)
#define MWVW_OFF   (TAIL_OFF + 5888)
#define K1_SMEM_BYTES 110592

__global__ __launch_bounds__(256, 2) void k1_main(
    const float* __restrict__ x, const int* __restrict__ mask,
    const float* __restrict__ hW1, const float* __restrict__ hg1,
    const float* __restrict__ hbt1,
    const float* __restrict__ hb2, const float* __restrict__ hg2,
    const float* __restrict__ hbt2)
{
    extern __shared__ char smem[];
    const uint32_t smem_u32 = smem_to_u32(smem);

    float4* c4s  = reinterpret_cast<float4*>(smem + C4S_OFF);
    float*  b2s  = reinterpret_cast<float*>(smem + B2S_OFF);
    float*  g2s  = reinterpret_cast<float*>(smem + G2S_OFF);
    float*  bt2s = reinterpret_cast<float*>(smem + BT2S_OFF);
    float*  xs_s = reinterpret_cast<float*>(smem + XS_OFF);
    float*  s_s  = reinterpret_cast<float*>(smem + SS_OFF);
    float*  ms_s = reinterpret_cast<float*>(smem + MS_OFF);
    float*  wm_s = reinterpret_cast<float*>(smem + WM_OFF);
    float*  mu2  = reinterpret_cast<float*>(smem + MU2_OFF);
    float*  is2  = reinterpret_cast<float*>(smem + IS2_OFF);
    float*  mwvw = reinterpret_cast<float*>(smem + MWVW_OFF);
    float*  gs   = reinterpret_cast<float*>(smem);   // stride 66, reuses A_hi

    const int tid = threadIdx.x;
    const int wid = tid >> 5;
    const int lid = tid & 31;
    const int jt = blockIdx.y;
    const int jbase = jt * 128;

    // ---- one-time setup ----
    {   // B planes: copy [d][k] rows (256B) into padded 272B rows
        const uint4* sh = g_Bh;
        const uint4* sl = g_Bl;
        #pragma unroll
        for (int it = 0; it < 4; it++) {
            const int i = it * 256 + tid;
            const int row = i >> 4, c = i & 15;
            *reinterpret_cast<uint4*>(smem + B_HI_OFF + row * 272 + c * 16) = sh[i];
            *reinterpret_cast<uint4*>(smem + B_LO_OFF + row * 272 + c * 16) = sl[i];
        }
    }
    if (tid < 128) {
        const float g1v = hg1[tid];
        c4s[tid] = make_float4(hW1[tid] * g1v, g1v, hbt1[tid], 0.f);
    } else if (tid < 192) {
        const int t = tid - 128;
        b2s[t] = hb2[t]; g2s[t] = hg2[t]; bt2s[t] = hbt2[t];
    } else if (tid < 224) {
        const int l = tid - 192;
        float s = 0.f, s2 = 0.f;
        #pragma unroll
        for (int kk = 0; kk < 4; kk++) { const float w = hW1[kk * 32 + l]; s += w; s2 += w * w; }
        #pragma unroll
        for (int o = 16; o > 0; o >>= 1) {
            s  += __shfl_xor_sync(0xffffffffu, s,  o);
            s2 += __shfl_xor_sync(0xffffffffu, s2, o);
        }
        if (l == 0) {
            const float mw = s * (1.f / 128.f);
            mwvw[0] = mw; mwvw[1] = s2 * (1.f / 128.f) - mw * mw;
        }
    }
    __syncthreads();

    // mainloop thread geometry
    const int jw = wid >> 1;          // 0..3 : j-block of 32
    const int dw = wid & 1;           // 0..1 : d-block of 32
    const int g  = lid >> 2;          // 0..7
    const int t  = lid & 3;           // 0..3
    const uint32_t a_base = smem_u32 + A_HI_OFF
        + (uint32_t)((jw * 32 + (lid & 15)) * 272 + (lid >> 4) * 16);
    const uint32_t b_base = smem_u32 + B_HI_OFF
        + (uint32_t)((dw * 32 + (lid >> 4) * 8 + (lid & 7)) * 272
                     + ((lid >> 3) & 1) * 16);

    // phase1 geometry
    const int pj = tid & 127;
    const int kh = tid >> 7;
    const uint32_t a_st = (uint32_t)(pj * 272 + kh * 128);

    for (int bb = 0; bb < 16; bb++) {
        const int b = blockIdx.x * 16 + bb;

        // ---- per-j analytic LN1 stats ----
        if (tid < 128) {
            const int j = jbase + tid;
            const float xv = x[b * 4096 + j];
            const float4 st = *reinterpret_cast<const float4*>(&g_stats[4 * j]);
            const float mw = mwvw[0], vw = mwvw[1];
            const float mu = xv * mw + st.x;
            const float var = xv * xv * vw + 2.f * xv * (st.z - mw * st.x)
                            + (st.y - st.x * st.x);
            const float s = rsqrtf(var + EPS);
            xs_s[tid] = xv * s;
            s_s[tid]  = s;
            ms_s[tid] = mu * s;
            wm_s[tid] = (mask[b * 4096 + j] > 0) ? 1.f : 0.f;
        }
        __syncthreads();

        // ---- phase1: A = relu(LN1) bf16 hi/lo planes, [j][k] rows 272B ----
        {
            const float sj = s_s[pj], xsv = xs_s[pj], msv = ms_s[pj];
            const float4* fat = reinterpret_cast<const float4*>(
                g_FAT + (jbase + pj) * 128 + kh * 64);
            #pragma unroll
            for (int gg = 0; gg < 8; gg++) {
                const float4 fa0 = fat[gg * 2];
                const float4 fa1 = fat[gg * 2 + 1];
                const float fav[8] = {fa0.x, fa0.y, fa0.z, fa0.w,
                                      fa1.x, fa1.y, fa1.z, fa1.w};
                float v[8];
                #pragma unroll
                for (int kk = 0; kk < 8; kk++) {
                    const float4 c = c4s[kh * 64 + gg * 8 + kk];
                    const float base = fmaf(c.x, xsv, fmaf(c.y, -msv, c.z));
                    v[kk] = fmaxf(fmaf(c.y * sj, fav[kk], base), 0.f);
                }
                uint32_t p[4], q[4];
                #pragma unroll
                for (int u = 0; u < 4; u++) {
                    CVT_BF16X2_F32(p[u], v[2 * u], v[2 * u + 1]);
                    const float f0 = __uint_as_float(p[u] << 16);
                    const float f1 = __uint_as_float(p[u] & 0xffff0000u);
                    CVT_BF16X2_F32(q[u], v[2 * u] - f0, v[2 * u + 1] - f1);
                }
                const uint32_t off = a_st + gg * 16;
                *reinterpret_cast<uint4*>(smem + A_HI_OFF + off) = make_uint4(p[0], p[1], p[2], p[3]);
                *reinterpret_cast<uint4*>(smem + A_LO_OFF + off) = make_uint4(q[0], q[1], q[2], q[3]);
            }
        }
        __syncthreads();

        // ---- mainloop: 8 k16-steps, 3-term bf16 mma ----
        float acc[2][4][4];
        #pragma unroll
        for (int jm = 0; jm < 2; jm++)
            #pragma unroll
            for (int dn = 0; dn < 4; dn++)
                #pragma unroll
                for (int r = 0; r < 4; r++) acc[jm][dn][r] = 0.f;

        #pragma unroll
        for (int ks = 0; ks < 8; ks++) {
            const uint32_t kb = ks * 32;
            uint32_t ah[2][4], al[2][4], bh[4][2], bl[4][2];
            ldsm4(ah[0], a_base + kb);
            ldsm4(ah[1], a_base + 16 * 272 + kb);
            ldsm4(al[0], a_base + (A_LO_OFF - A_HI_OFF) + kb);
            ldsm4(al[1], a_base + (A_LO_OFF - A_HI_OFF) + 16 * 272 + kb);
            ldsm4(&bh[0][0], b_base + kb);
            ldsm4(&bh[2][0], b_base + 16 * 272 + kb);
            ldsm4(&bl[0][0], b_base + (B_LO_OFF - B_HI_OFF) + kb);
            ldsm4(&bl[2][0], b_base + (B_LO_OFF - B_HI_OFF) + 16 * 272 + kb);
            #pragma unroll
            for (int jm = 0; jm < 2; jm++)
                #pragma unroll
                for (int dn = 0; dn < 4; dn++) {
                    mma_bf16(acc[jm][dn], ah[jm], bh[dn][0], bh[dn][1]);
                    mma_bf16(acc[jm][dn], ah[jm], bl[dn][0], bl[dn][1]);
                    mma_bf16(acc[jm][dn], al[jm], bh[dn][0], bh[dn][1]);
                }
        }
        __syncthreads();   // A reads done; reuse A_hi region as gs

        // ---- epilogue: +hb2 -> gs [j][d] stride 66 ----
        #pragma unroll
        for (int jm = 0; jm < 2; jm++) {
            const int j0 = jw * 32 + jm * 16 + g;
            #pragma unroll
            for (int dn = 0; dn < 4; dn++) {
                const int d = dw * 32 + dn * 8 + t * 2;
                const float* c = acc[jm][dn];
                gs[j0 * 66 + d]           = c[0] + b2s[d];
                gs[j0 * 66 + d + 1]       = c[1] + b2s[d + 1];
                gs[(j0 + 8) * 66 + d]     = c[2] + b2s[d];
                gs[(j0 + 8) * 66 + d + 1] = c[3] + b2s[d + 1];
            }
        }
        __syncthreads();

        // ---- LN2 stats per row ----
        if (tid < 128) {
            float s = 0.f, s2 = 0.f;
            #pragma unroll 8
            for (int d = 0; d < 64; d++) { const float v = gs[tid * 66 + d]; s += v; s2 += v * v; }
            const float mu = s * (1.f / 64.f);
            const float var = s2 * (1.f / 64.f) - mu * mu;
            mu2[tid] = mu;
            is2[tid] = rsqrtf(var + EPS);
        }
        __syncthreads();

        // ---- masked pool over 128 j (warps 0-1) + count (warp 2) ----
        if (tid < 64) {
            float a = 0.f;
            #pragma unroll 8
            for (int j = 0; j < 128; j++) {
                const float v = (gs[j * 66 + tid] - mu2[j]) * is2[j] * g2s[tid] + bt2s[tid];
                a += wm_s[j] * fmaxf(v, 0.f);
            }
            g_part[(jt * 128 + b) * 64 + tid] = a;
        } else if (wid == 2) {
            float c = wm_s[lid] + wm_s[lid + 32] + wm_s[lid + 64] + wm_s[lid + 96];
            #pragma unroll
            for (int o = 16; o > 0; o >>= 1) c += __shfl_xor_sync(0xffffffffu, c, o);
            if (lid == 0) g_cnt[jt * 128 + b] = c;
        }
        __syncthreads();
    }
}

// ============================================================================
// K2: per-b reduction + head MLP. 128 blocks x 256 threads.
// ILP-restructured: 4 accumulators per GEMV chain, phase C over 256 threads,
// mask count read from g_cnt (fused in k1).
// ============================================================================
__global__ __launch_bounds__(256) void k2_head(
    const float* __restrict__ eW1, const float* __restrict__ eb1,
    const float* __restrict__ eW2, const float* __restrict__ eb2,
    float* __restrict__ out)
{
    __shared__ float c_s[64];
    __shared__ float e_s[256];
    __shared__ float red[16];
    __shared__ float part[4][65];
    __shared__ float os[64];
    __shared__ float sc[4];

    const int b = blockIdx.x;
    const int tid = threadIdx.x;
    const int wid = tid >> 5;
    const int lid = tid & 31;

    // pooled partial reduction (warps 0-1) with 4-way ILP
    float s = 0.f;
    if (tid < 64) {
        float a0 = 0.f, a1 = 0.f, a2 = 0.f, a3 = 0.f;
        #pragma unroll
        for (int jt = 0; jt < 8; jt++) {
            a0 += g_part[((4 * jt + 0) * 128 + b) * 64 + tid];
            a1 += g_part[((4 * jt + 1) * 128 + b) * 64 + tid];
            a2 += g_part[((4 * jt + 2) * 128 + b) * 64 + tid];
            a3 += g_part[((4 * jt + 3) * 128 + b) * 64 + tid];
        }
        s = (a0 + a1) + (a2 + a3);
    } else if (wid == 2) {
        // observed count: 32 partials, one per jt
        float c = g_cnt[lid * 128 + b];
        #pragma unroll
        for (int o = 16; o > 0; o >>= 1) c += __shfl_xor_sync(0xffffffffu, c, o);
        if (lid == 0) sc[0] = fmaxf(c, 1.f);
    }
    __syncthreads();
    if (tid < 64) c_s[tid] = s / sc[0];
    __syncthreads();

    // e = relu(LN_na(c @ eW1 + eb1)), E = 256; 4-way ILP
    float t;
    {
        float a0 = 0.f, a1 = 0.f, a2 = 0.f, a3 = 0.f;
        #pragma unroll
        for (int d4 = 0; d4 < 16; d4++) {
            a0 += c_s[4 * d4 + 0] * eW1[(4 * d4 + 0) * 256 + tid];
            a1 += c_s[4 * d4 + 1] * eW1[(4 * d4 + 1) * 256 + tid];
            a2 += c_s[4 * d4 + 2] * eW1[(4 * d4 + 2) * 256 + tid];
            a3 += c_s[4 * d4 + 3] * eW1[(4 * d4 + 3) * 256 + tid];
        }
        t = eb1[tid] + (a0 + a1) + (a2 + a3);
    }
    {
        float s1 = t, s2 = t * t;
        #pragma unroll
        for (int o = 16; o > 0; o >>= 1) {
            s1 += __shfl_xor_sync(0xffffffffu, s1, o);
            s2 += __shfl_xor_sync(0xffffffffu, s2, o);
        }
        if (lid == 0) { red[wid] = s1; red[8 + wid] = s2; }
        __syncthreads();
        if (tid == 0) {
            float S1 = 0.f, S2 = 0.f;
            #pragma unroll
            for (int w = 0; w < 8; w++) { S1 += red[w]; S2 += red[8 + w]; }
            const float mu = S1 * (1.f / 256.f);
            const float var = S2 * (1.f / 256.f) - mu * mu;
            sc[1] = mu; sc[2] = rsqrtf(var + EPS);
        }
        __syncthreads();
    }
    e_s[tid] = fmaxf(0.f, (t - sc[1]) * sc[2]);
    __syncthreads();

    // out = relu(LN_na(e @ eW2 + eb2)); partials over 4 i-quarters x 64 d
    {
        const int q = tid >> 6;           // 0..3
        const int d = tid & 63;
        float a0 = 0.f, a1 = 0.f, a2 = 0.f, a3 = 0.f;
        #pragma unroll
        for (int i4 = 0; i4 < 16; i4++) {
            const int i = q * 64 + 4 * i4;
            a0 += e_s[i + 0] * eW2[(i + 0) * 64 + d];
            a1 += e_s[i + 1] * eW2[(i + 1) * 64 + d];
            a2 += e_s[i + 2] * eW2[(i + 2) * 64 + d];
            a3 += e_s[i + 3] * eW2[(i + 3) * 64 + d];
        }
        part[q][d] = (a0 + a1) + (a2 + a3);
    }
    __syncthreads();
    if (tid < 64)
        os[tid] = part[0][tid] + part[1][tid] + part[2][tid] + part[3][tid] + eb2[tid];
    __syncthreads();
    if (tid < 32) {
        const float a = os[tid], c = os[tid + 32];
        float s1 = a + c, s2 = a * a + c * c;
        #pragma unroll
        for (int o = 16; o > 0; o >>= 1) {
            s1 += __shfl_xor_sync(0xffffffffu, s1, o);
            s2 += __shfl_xor_sync(0xffffffffu, s2, o);
        }
        if (tid == 0) {
            const float mu = s1 * (1.f / 64.f);
            const float var = s2 * (1.f / 64.f) - mu * mu;
            sc[1] = mu; sc[2] = rsqrtf(var + EPS);
        }
    }
    __syncthreads();
    if (tid < 64) {
        const float v = fmaxf(0.f, (os[tid] - sc[1]) * sc[2]);
        if (tid < 32) out[b * 32 + tid] = v;                   // mu
        else          out[128 * 32 + b * 32 + (tid - 32)] = v; // logvar
    }
}

// ============================================================================
extern "C" void kernel_launch(void* const* d_in, const int* in_sizes, int n_in,
                              void* d_out, int out_size)
{
    const float* x    = (const float*)d_in[0];
    const int*   mask = (const int*)  d_in[1];
    const float* F    = (const float*)d_in[2];
    const float* hW1  = (const float*)d_in[3];
    const float* hb1  = (const float*)d_in[4];
    const float* hg1  = (const float*)d_in[5];
    const float* hbt1 = (const float*)d_in[6];
    const float* hW2  = (const float*)d_in[7];
    const float* hb2  = (const float*)d_in[8];
    const float* hg2  = (const float*)d_in[9];
    const float* hbt2 = (const float*)d_in[10];
    const float* eW1  = (const float*)d_in[11];
    const float* eb1  = (const float*)d_in[12];
    const float* eW2  = (const float*)d_in[13];
    const float* eb2  = (const float*)d_in[14];
    float* out = (float*)d_out;

    cudaFuncSetAttribute(k1_main, cudaFuncAttributeMaxDynamicSharedMemorySize,
                         K1_SMEM_BYTES);

    k0_precompute<<<256, 256>>>(F, hW1, hb1);
    k0b_prepB<<<32, 256>>>(hW2);
    dim3 g1(8, 32);
    k1_main<<<g1, 256, K1_SMEM_BYTES>>>(x, mask, hW1, hg1, hbt1,
                                        hb2, hg2, hbt2);
    k2_head<<<128, 256>>>(eW1, eb1, eW2, eb2, out);
}